// round 1
// baseline (speedup 1.0000x reference)
#include <cuda_runtime.h>
#include <cuda_fp16.h>
#include <cuda_fp8.h>
#include <cstdint>

using u32 = unsigned int;

#define BM   128
#define BK   64
#define KDIM 1024
#define NOUT 58
#define NCLS 12

// ---------------- device scratch (no allocations allowed) ----------------
__device__ __half g_w1q[64 * 1024];   // e4m3-valued W1 as f16, rows 58..63 zero
__device__ float  g_w2f[64 * 16];     // e4m3-valued W2 transposed [d][c], zero padded
__device__ float  g_bn[3 * 64];       // [inv | mean | beta], zero padded

// ---------------- helpers ----------------
// fake-quant through hw e4m3 (satfinite, RNE) -> exact f16 pair packed in u32
__device__ __forceinline__ u32 q2h(float a, float b) {
    __nv_fp8x2_storage_t f8 =
        __nv_cvt_float2_to_fp8x2(make_float2(a, b), __NV_SATFINITE, __NV_E4M3);
    __half2_raw h2 = __nv_cvt_fp8x2_to_halfraw2(f8, __NV_E4M3);
    return (u32)h2.x | ((u32)h2.y << 16);
}

__device__ __forceinline__ float qf(float a) {
    __nv_fp8_storage_t f8 = __nv_cvt_float_to_fp8(a, __NV_SATFINITE, __NV_E4M3);
    __half_raw hr = __nv_cvt_fp8_to_halfraw(f8, __NV_E4M3);
    return __half2float(__half(hr));
}

__device__ __forceinline__ void mma16816(float* c, const u32* a, const u32* b) {
    asm volatile(
        "mma.sync.aligned.m16n8k16.row.col.f32.f16.f16.f32 "
        "{%0,%1,%2,%3}, {%4,%5,%6,%7}, {%8,%9}, {%0,%1,%2,%3};\n"
        : "+f"(c[0]), "+f"(c[1]), "+f"(c[2]), "+f"(c[3])
        : "r"(a[0]), "r"(a[1]), "r"(a[2]), "r"(a[3]), "r"(b[0]), "r"(b[1]));
}

// ---------------- prep: quantize weights, fold BN ----------------
__global__ void prep_kernel(const float* __restrict__ W1, const float* __restrict__ W2,
                            const float* __restrict__ gamma, const float* __restrict__ beta,
                            const float* __restrict__ mean, const float* __restrict__ var) {
    int o = blockIdx.x;  // 0..63
    for (int k = threadIdx.x; k < KDIM; k += blockDim.x) {
        float v = (o < NOUT) ? W1[o * KDIM + k] : 0.f;
        __nv_fp8_storage_t f8 = __nv_cvt_float_to_fp8(v, __NV_SATFINITE, __NV_E4M3);
        __half_raw hr = __nv_cvt_fp8_to_halfraw(f8, __NV_E4M3);
        g_w1q[o * KDIM + k] = __half(hr);
    }
    if (blockIdx.x == 0) {
        for (int i = threadIdx.x; i < 1024; i += blockDim.x) {
            int d = i >> 4, c = i & 15;
            float v = (d < NOUT && c < NCLS) ? W2[c * NOUT + d] : 0.f;
            g_w2f[i] = qf(v);
        }
        if (threadIdx.x < 64) {
            int d = threadIdx.x;
            float inv = 0.f, m = 0.f, b = 0.f;
            if (d < NOUT) {
                inv = gamma[d] / sqrtf(var[d] + 1e-5f);
                m = mean[d];
                b = beta[d];
            }
            g_bn[d] = inv; g_bn[64 + d] = m; g_bn[128 + d] = b;
        }
    }
}

// ---------------- fused: quant -> GEMM1 (tensor cores) -> BN/ReLU/uq/quant -> GEMM2 ----------------
__global__ void __launch_bounds__(256) fused_kernel(const float* __restrict__ x,
                                                    const float* __restrict__ act_scale,
                                                    float* __restrict__ out) {
    // phase 1 layout: xs u32[2][128][32] @0 (32KB), ws u32[2][64][32] @32768 (16KB) = 48KB
    // phase 2 layout (reuse): aqs half[128][68] @0, w2f f32[64][16] @17408, bn @21504
    __shared__ __align__(16) unsigned char smem[49152];
    u32* xsw = reinterpret_cast<u32*>(smem);
    u32* wsw = reinterpret_cast<u32*>(smem + 32768);

    const int t = threadIdx.x;
    const int lane = t & 31, wid = t >> 5;
    const int wm = wid >> 1, wn = wid & 1;   // 4x2 warp grid, 32x32 per warp
    const int g = lane >> 2, tig = lane & 3;
    const long long B0 = (long long)blockIdx.x * BM;

    float acc[2][4][4];
#pragma unroll
    for (int i = 0; i < 2; i++)
#pragma unroll
        for (int j = 0; j < 4; j++)
#pragma unroll
            for (int k = 0; k < 4; k++) acc[i][j][k] = 0.f;

    float4 xr[8];
    float4 wr[2];

    auto load_global = [&](int kt) {
        const float4* xg = reinterpret_cast<const float4*>(x);
#pragma unroll
        for (int it = 0; it < 8; it++) {
            int i = t + 256 * it;
            int row = i >> 4, c4 = i & 15;
            xr[it] = xg[(B0 + row) * 256 + kt * 16 + c4];
        }
#pragma unroll
        for (int it = 0; it < 2; it++) {
            int fi = t + 256 * it;
            int n = fi >> 3, seg = fi & 7;
            wr[it] = *reinterpret_cast<const float4*>(g_w1q + n * KDIM + kt * 64 + seg * 8);
        }
    };

    auto store_smem = [&](int buf) {
        u32* xb = xsw + buf * (128 * 32);
        u32* wb = wsw + buf * (64 * 32);
#pragma unroll
        for (int it = 0; it < 8; it++) {
            int i = t + 256 * it;
            int row = i >> 4, c4 = i & 15;
            uint2 v;
            v.x = q2h(xr[it].x, xr[it].y);
            v.y = q2h(xr[it].z, xr[it].w);
            int idx = row * 32 + ((c4 * 2) ^ (4 * (row & 7)));  // XOR swizzle, keeps pair adjacency
            *reinterpret_cast<uint2*>(xb + idx) = v;
        }
#pragma unroll
        for (int it = 0; it < 2; it++) {
            int fi = t + 256 * it;
            int n = fi >> 3, seg = fi & 7;
            int idx = n * 32 + ((seg * 4) ^ (4 * (n & 7)));
            *reinterpret_cast<float4*>(wb + idx) = wr[it];
        }
    };

    auto compute = [&](int buf) {
        const u32* xb = xsw + buf * (128 * 32);
        const u32* wb = wsw + buf * (64 * 32);
#pragma unroll
        for (int kk = 0; kk < 4; kk++) {
            u32 a[2][4], b[4][2];
#pragma unroll
            for (int mi = 0; mi < 2; mi++) {
                int r0 = wm * 32 + mi * 16 + g;     // (r0 & 7) == g
                int sw = 4 * g;
                int w0 = (kk * 8 + tig) ^ sw;
                int w1 = (kk * 8 + tig + 4) ^ sw;
                a[mi][0] = xb[r0 * 32 + w0];
                a[mi][1] = xb[(r0 + 8) * 32 + w0];
                a[mi][2] = xb[r0 * 32 + w1];
                a[mi][3] = xb[(r0 + 8) * 32 + w1];
            }
#pragma unroll
            for (int ni = 0; ni < 4; ni++) {
                int n = wn * 32 + ni * 8 + g;       // (n & 7) == g
                int sw = 4 * g;
                b[ni][0] = wb[n * 32 + ((kk * 8 + tig) ^ sw)];
                b[ni][1] = wb[n * 32 + ((kk * 8 + tig + 4) ^ sw)];
            }
#pragma unroll
            for (int mi = 0; mi < 2; mi++)
#pragma unroll
                for (int ni = 0; ni < 4; ni++) mma16816(acc[mi][ni], a[mi], b[ni]);
        }
    };

    // ---- mainloop: 16 chunks of K=64, reg-staged double buffering ----
    load_global(0);
    store_smem(0);
    __syncthreads();
#pragma unroll 1
    for (int kt = 0; kt < 16; kt++) {
        if (kt < 15) load_global(kt + 1);
        compute(kt & 1);
        if (kt < 15) store_smem((kt + 1) & 1);
        __syncthreads();
    }

    // ---- epilogue: BN -> ReLU -> uint8 affine quant -> e4m3 quant -> smem ----
    __half* aqs = reinterpret_cast<__half*>(smem);          // [128][68] halves
    u32* aqw = reinterpret_cast<u32*>(smem);
    float* w2f = reinterpret_cast<float*>(smem + 17408);    // [64][16]
    float* bni = reinterpret_cast<float*>(smem + 21504);
    float* bnm = bni + 64;
    float* bnb = bni + 128;

    for (int i = t; i < 1024; i += 256) w2f[i] = g_w2f[i];
    if (t < 64) { bni[t] = g_bn[t]; bnm[t] = g_bn[64 + t]; bnb[t] = g_bn[128 + t]; }
    const float s_act = act_scale[0];
    __syncthreads();

#pragma unroll
    for (int mi = 0; mi < 2; mi++) {
#pragma unroll
        for (int ni = 0; ni < 4; ni++) {
            int d0 = wn * 32 + ni * 8 + tig * 2;
            float i0 = bni[d0], i1 = bni[d0 + 1];
            float m0 = bnm[d0], m1 = bnm[d0 + 1];
            float e0 = bnb[d0], e1 = bnb[d0 + 1];
            int rA = wm * 32 + mi * 16 + g;
#pragma unroll
            for (int v = 0; v < 2; v++) {
                int row = rA + v * 8;
                float h0 = acc[mi][ni][v * 2 + 0];
                float h1 = acc[mi][ni][v * 2 + 1];
                h0 = (h0 - m0) * i0 + e0;
                h1 = (h1 - m1) * i1 + e1;
                h0 = fmaxf(h0, 0.f);
                h1 = fmaxf(h1, 0.f);
                float r0 = fminf(rintf(__fdiv_rn(h0, s_act)), 255.f);  // RNE, exact div = jnp.round(x/s)
                float r1 = fminf(rintf(__fdiv_rn(h1, s_act)), 255.f);
                float a0 = r0 * s_act, a1 = r1 * s_act;
                aqw[row * 34 + (d0 >> 1)] = q2h(a0, a1);               // mf_quant(a) as f16
            }
        }
    }
    __syncthreads();

    // ---- GEMM2: out[b, c] = sum_d aq[b][d] * w2q[c][d], 12 cols ----
    {
        int row = t >> 1;
        int cb = (t & 1) * 6;
        float o2[6] = {0.f, 0.f, 0.f, 0.f, 0.f, 0.f};
#pragma unroll 1
        for (int d = 0; d < NOUT; d++) {
            float av = __half2float(aqs[row * 68 + d]);
#pragma unroll
            for (int j = 0; j < 6; j++) o2[j] = fmaf(av, w2f[d * 16 + cb + j], o2[j]);
        }
#pragma unroll
        for (int j = 0; j < 6; j++) out[(B0 + row) * NCLS + cb + j] = o2[j];
    }
}

// ---------------- launch ----------------
extern "C" void kernel_launch(void* const* d_in, const int* in_sizes, int n_in,
                              void* d_out, int out_size) {
    const float* x      = (const float*)d_in[0];
    const float* W1     = (const float*)d_in[1];
    const float* W2     = (const float*)d_in[2];
    const float* gammaP = (const float*)d_in[3];
    const float* betaP  = (const float*)d_in[4];
    const float* meanP  = (const float*)d_in[5];
    const float* varP   = (const float*)d_in[6];
    const float* ascale = (const float*)d_in[7];
    float* out = (float*)d_out;

    int B = in_sizes[0] / KDIM;  // 65536

    prep_kernel<<<64, 256>>>(W1, W2, gammaP, betaP, meanP, varP);
    fused_kernel<<<B / BM, 256>>>(x, ascale, out);
}